// round 8
// baseline (speedup 1.0000x reference)
#include <cuda_runtime.h>
#include <cuda_bf16.h>
#include <limits.h>

// Scratch for per-batch chirp metadata (raw sn/en/s0/e0).
#define MAX_BN (32 * 256)
__device__ int g_sn[MAX_BN];
__device__ int g_en[MAX_BN];
__device__ int g_s0[MAX_BN];
__device__ int g_e0[MAX_BN];

// ---------------------------------------------------------------------------
// Kernel 1: per-batch prefix scan over chirp widths.
// ---------------------------------------------------------------------------
__global__ void tb_meta_kernel(const int* __restrict__ xi,
                               const int* __restrict__ Narr,
                               float* __restrict__ out_xi,
                               int n_max)
{
    extern __shared__ int sh[]; // n_max ints
    const int b = blockIdx.x;
    const int i = threadIdx.x;

    const int s0 = xi[(b * n_max + i) * 2 + 0];
    const int e0 = xi[(b * n_max + i) * 2 + 1];
    const int Nb = Narr[b];
    const bool valid = (i < Nb);

    int w = e0 - s0;
    if (w < 0) w = 0;
    const int wv = valid ? w : 0;

    sh[i] = wv;
    __syncthreads();
    for (int off = 1; off < n_max; off <<= 1) {
        int v = (i >= off) ? sh[i - off] : 0;
        __syncthreads();
        sh[i] += v;
        __syncthreads();
    }
    const int csum = sh[i];

    const int sn = csum - wv + i;
    const int en = csum + i;

    const int base = b * n_max + i;
    g_sn[base] = sn;
    g_en[base] = en;
    g_s0[base] = s0;
    g_e0[base] = e0;

    out_xi[base * 2 + 0] = valid ? (float)sn : 0.0f;
    out_xi[base * 2 + 1] = valid ? (float)en : 0.0f;
}

// ---------------------------------------------------------------------------
// Kernel 2: main gather. grid = (ceil(w_out/128), B) = 784 blocks,
// block = (128, 2) = 256 thr, forced <=42 regs so 6 blocks/SM resident
// -> 888 slots >= 784 blocks -> SINGLE WAVE, no tail.
// Each thread owns one output column t and 64 rows; inner loop batches 8
// independent LDGs before their 8 STGs (MLP ~ 8).
// ---------------------------------------------------------------------------
__global__ __launch_bounds__(256, 6)
void tb_main_kernel(const float* __restrict__ x,
                    const int* __restrict__ xl,
                    const float* __restrict__ sep_param,
                    const int* __restrict__ Narr,
                    float* __restrict__ out_x,
                    float* __restrict__ out_xl,
                    int rows, int W, int w_out, int n_max)
{
    __shared__ int s_sn[256], s_en[256], s_s0[256], s_e0[256];
    __shared__ int s_Nb;

    const int b = blockIdx.y;
    const int tid = threadIdx.y * blockDim.x + threadIdx.x;

    if (tid < n_max) {
        const int base = b * n_max + tid;
        s_sn[tid] = g_sn[base];
        s_en[tid] = g_en[base];
        s_s0[tid] = g_s0[base];
        s_e0[tid] = g_e0[base];
    }
    if (tid == 0) s_Nb = Narr[b];
    __syncthreads();

    const int t = blockIdx.x * blockDim.x + threadIdx.x;
    if (t >= w_out) return;

    const int Nb = s_Nb;

    // i = count of valid chirps with en <= t (en strictly increasing on valid part)
    int lo = 0, hi = n_max;
    while (lo < hi) {
        const int mid = (lo + hi) >> 1;
        const int e = (mid < Nb) ? s_en[mid] : INT_MAX;
        if (e <= t) lo = mid + 1; else hi = mid;
    }
    const int i = lo;
    const int ic = min(i, n_max - 1);

    const int sn_i = s_sn[ic];
    const int en_i = s_en[ic];
    const int s0_i = s_s0[ic];
    const int e0_i = s_e0[ic];

    const bool in_chirp = (i < Nb) && (t >= sn_i) && (en_i > sn_i) && (e0_i > s0_i);

    int src = s0_i + (t - sn_i);
    src = min(max(src, 0), W - 1);

    const int jp = min(max(i - 1, 0), n_max - 1);
    const int en_prev = s_en[jp];
    const bool is_sep = (i >= 1) && (t == en_prev) && ((i - 1) < (Nb - 1)) && (en_prev < W);

    const float fill = is_sep ? sep_param[0] : 0.0f;

    const float* __restrict__ xcol = x + (size_t)b * rows * W + src;
    float* __restrict__ ocol = out_x + (size_t)b * rows * w_out + t;

    const int ystep = 2;                    // blockDim.y
    if (in_chirp) {
        int h = threadIdx.y;
        for (; h + 7 * ystep < rows; h += 8 * ystep) {
            float v0 = __ldcs(xcol + (size_t)(h + 0 * ystep) * W);
            float v1 = __ldcs(xcol + (size_t)(h + 1 * ystep) * W);
            float v2 = __ldcs(xcol + (size_t)(h + 2 * ystep) * W);
            float v3 = __ldcs(xcol + (size_t)(h + 3 * ystep) * W);
            float v4 = __ldcs(xcol + (size_t)(h + 4 * ystep) * W);
            float v5 = __ldcs(xcol + (size_t)(h + 5 * ystep) * W);
            float v6 = __ldcs(xcol + (size_t)(h + 6 * ystep) * W);
            float v7 = __ldcs(xcol + (size_t)(h + 7 * ystep) * W);
            __stcs(ocol + (size_t)(h + 0 * ystep) * w_out, v0);
            __stcs(ocol + (size_t)(h + 1 * ystep) * w_out, v1);
            __stcs(ocol + (size_t)(h + 2 * ystep) * w_out, v2);
            __stcs(ocol + (size_t)(h + 3 * ystep) * w_out, v3);
            __stcs(ocol + (size_t)(h + 4 * ystep) * w_out, v4);
            __stcs(ocol + (size_t)(h + 5 * ystep) * w_out, v5);
            __stcs(ocol + (size_t)(h + 6 * ystep) * w_out, v6);
            __stcs(ocol + (size_t)(h + 7 * ystep) * w_out, v7);
        }
        for (; h < rows; h += ystep)
            __stcs(ocol + (size_t)h * w_out, __ldcs(xcol + (size_t)h * W));
    } else {
        int h = threadIdx.y;
        for (; h + 7 * ystep < rows; h += 8 * ystep) {
            __stcs(ocol + (size_t)(h + 0 * ystep) * w_out, fill);
            __stcs(ocol + (size_t)(h + 1 * ystep) * w_out, fill);
            __stcs(ocol + (size_t)(h + 2 * ystep) * w_out, fill);
            __stcs(ocol + (size_t)(h + 3 * ystep) * w_out, fill);
            __stcs(ocol + (size_t)(h + 4 * ystep) * w_out, fill);
            __stcs(ocol + (size_t)(h + 5 * ystep) * w_out, fill);
            __stcs(ocol + (size_t)(h + 6 * ystep) * w_out, fill);
            __stcs(ocol + (size_t)(h + 7 * ystep) * w_out, fill);
        }
        for (; h < rows; h += ystep)
            __stcs(ocol + (size_t)h * w_out, fill);
    }

    if (threadIdx.y == 0) {
        int xlv = in_chirp ? xl[b * W + src] : (is_sep ? 2 : 0);
        out_xl[(size_t)b * w_out + t] = (float)xlv;
    }
}

// ---------------------------------------------------------------------------
// Launch. Inputs (metadata order): x f32, xi i32, N i32, xl i32, sep_param f32,
// w_out scalar (derived from out_size instead).
// Output buffer (f32): concat(x_new, xi_new, xl_new) flattened.
// ---------------------------------------------------------------------------
extern "C" void kernel_launch(void* const* d_in, const int* in_sizes, int n_in,
                              void* d_out, int out_size)
{
    const float* x   = (const float*)d_in[0];
    const int*   xi  = (const int*)  d_in[1];
    const int*   Nn  = (const int*)  d_in[2];
    const int*   xl  = (const int*)  d_in[3];
    const float* sep = (const float*)d_in[4];

    const int B     = in_sizes[2];
    const int n_max = in_sizes[1] / (2 * B);
    const int W     = in_sizes[3] / B;
    const int rows  = in_sizes[0] / (B * W);           // C * H
    const int w_out = (out_size - B * n_max * 2) / (B * (rows + 1));

    float* out_x  = (float*)d_out;
    float* out_xi = out_x + (size_t)B * rows * w_out;
    float* out_xl = out_xi + (size_t)B * n_max * 2;

    tb_meta_kernel<<<B, n_max, n_max * sizeof(int)>>>(xi, Nn, out_xi, n_max);

    dim3 block(128, 2);
    dim3 grid((w_out + 127) / 128, B);
    tb_main_kernel<<<grid, block>>>(x, xl, sep, Nn, out_x, out_xl,
                                    rows, W, w_out, n_max);
}

// round 9
// speedup vs baseline: 1.0769x; 1.0769x over previous
#include <cuda_runtime.h>
#include <cuda_bf16.h>
#include <limits.h>

// Scratch for per-batch chirp metadata (raw sn/en/s0/e0).
#define MAX_BN (32 * 256)
__device__ int g_sn[MAX_BN];
__device__ int g_en[MAX_BN];
__device__ int g_s0[MAX_BN];
__device__ int g_e0[MAX_BN];

// ---------------------------------------------------------------------------
// Kernel 1: per-batch prefix scan over chirp widths.
// ---------------------------------------------------------------------------
__global__ void tb_meta_kernel(const int* __restrict__ xi,
                               const int* __restrict__ Narr,
                               float* __restrict__ out_xi,
                               int n_max)
{
    extern __shared__ int sh[];
    const int b = blockIdx.x;
    const int i = threadIdx.x;

    const int s0 = xi[(b * n_max + i) * 2 + 0];
    const int e0 = xi[(b * n_max + i) * 2 + 1];
    const int Nb = Narr[b];
    const bool valid = (i < Nb);

    int w = e0 - s0;
    if (w < 0) w = 0;
    const int wv = valid ? w : 0;

    sh[i] = wv;
    __syncthreads();
    for (int off = 1; off < n_max; off <<= 1) {
        int v = (i >= off) ? sh[i - off] : 0;
        __syncthreads();
        sh[i] += v;
        __syncthreads();
    }
    const int csum = sh[i];

    const int sn = csum - wv + i;
    const int en = csum + i;

    const int base = b * n_max + i;
    g_sn[base] = sn;
    g_en[base] = en;
    g_s0[base] = s0;
    g_e0[base] = e0;

    out_xi[base * 2 + 0] = valid ? (float)sn : 0.0f;
    out_xi[base * 2 + 1] = valid ? (float)en : 0.0f;
}

// ---------------------------------------------------------------------------
// Shared column-classification logic (search + flags).
// ---------------------------------------------------------------------------
template<int NMAX>
__device__ __forceinline__ void classify(
    const int* s_sn, const int* s_en, const int* s_s0, const int* s_e0,
    int Nb, int t, int W,
    bool& in_chirp, bool& is_sep, int& src)
{
    int lo = 0, hi = NMAX;
    #pragma unroll
    for (int step = 0; step < 31; step++) {
        if (lo >= hi) break;
        const int mid = (lo + hi) >> 1;
        const int e = (mid < Nb) ? s_en[mid] : INT_MAX;
        if (e <= t) lo = mid + 1; else hi = mid;
    }
    const int i = lo;
    const int ic = min(i, NMAX - 1);

    const int sn_i = s_sn[ic];
    const int en_i = s_en[ic];
    const int s0_i = s_s0[ic];
    const int e0_i = s_e0[ic];

    in_chirp = (i < Nb) && (t >= sn_i) && (en_i > sn_i) && (e0_i > s0_i);
    src = min(max(s0_i + (t - sn_i), 0), W - 1);

    const int jp = min(max(i - 1, 0), NMAX - 1);
    const int en_prev = s_en[jp];
    is_sep = (i >= 1) && (t == en_prev) && ((i - 1) < (Nb - 1)) && (en_prev < W);
}

// ---------------------------------------------------------------------------
// Kernel 2 (specialized): compile-time shapes -> immediate-offset LDG/STG,
// explicit 2-stage software pipeline (prefetch batch k+1 before storing k).
// block (128,2); each thread: 1 column, 64 rows in 8 batches of 8.
// ---------------------------------------------------------------------------
template<int ROWS, int WC, int WOUTC, int NMAX>
__global__ __launch_bounds__(256, 6)
void tb_main_tpl(const float* __restrict__ x,
                 const int* __restrict__ xl,
                 const float* __restrict__ sep_param,
                 const int* __restrict__ Narr,
                 float* __restrict__ out_x,
                 float* __restrict__ out_xl)
{
    __shared__ int s_sn[NMAX], s_en[NMAX], s_s0[NMAX], s_e0[NMAX];
    __shared__ int s_Nb;

    const int b = blockIdx.y;
    const int tid = threadIdx.y * 128 + threadIdx.x;

    if (tid < NMAX) {
        const int base = b * NMAX + tid;
        s_sn[tid] = g_sn[base];
        s_en[tid] = g_en[base];
        s_s0[tid] = g_s0[base];
        s_e0[tid] = g_e0[base];
    }
    if (tid == 0) s_Nb = Narr[b];
    __syncthreads();

    const int t = blockIdx.x * 128 + threadIdx.x;
    if (t >= WOUTC) return;

    bool in_chirp, is_sep; int src;
    classify<NMAX>(s_sn, s_en, s_s0, s_e0, s_Nb, t, WC, in_chirp, is_sep, src);

    const float fill = is_sep ? sep_param[0] : 0.0f;
    const int ty = threadIdx.y;                     // 0..1

    const float* __restrict__ xcol = x + (size_t)b * ROWS * WC + src
                                       + (size_t)ty * WC;
    float* __restrict__ ocol = out_x + (size_t)b * ROWS * WOUTC + t
                                     + (size_t)ty * WOUTC;

    constexpr int NB = ROWS / 16;                   // batches of 8 rows (ystep 2)

    if (in_chirp) {
        float cur[8];
        #pragma unroll
        for (int k = 0; k < 8; k++)
            cur[k] = __ldcs(xcol + (size_t)(2 * k) * WC);
        #pragma unroll
        for (int bt = 0; bt < NB; bt++) {
            float nxt[8];
            if (bt + 1 < NB) {
                #pragma unroll
                for (int k = 0; k < 8; k++)
                    nxt[k] = __ldcs(xcol + (size_t)((bt + 1) * 16 + 2 * k) * WC);
            }
            #pragma unroll
            for (int k = 0; k < 8; k++)
                __stcs(ocol + (size_t)(bt * 16 + 2 * k) * WOUTC, cur[k]);
            if (bt + 1 < NB) {
                #pragma unroll
                for (int k = 0; k < 8; k++) cur[k] = nxt[k];
            }
        }
    } else {
        #pragma unroll
        for (int bt = 0; bt < NB; bt++) {
            #pragma unroll
            for (int k = 0; k < 8; k++)
                __stcs(ocol + (size_t)(bt * 16 + 2 * k) * WOUTC, fill);
        }
    }

    if (ty == 0) {
        int xlv = in_chirp ? xl[b * WC + src] : (is_sep ? 2 : 0);
        out_xl[(size_t)b * WOUTC + t] = (float)xlv;
    }
}

// ---------------------------------------------------------------------------
// Kernel 2 (generic fallback): runtime shapes, batched MLP-8 loop.
// ---------------------------------------------------------------------------
__global__ __launch_bounds__(256, 6)
void tb_main_kernel(const float* __restrict__ x,
                    const int* __restrict__ xl,
                    const float* __restrict__ sep_param,
                    const int* __restrict__ Narr,
                    float* __restrict__ out_x,
                    float* __restrict__ out_xl,
                    int rows, int W, int w_out, int n_max)
{
    __shared__ int s_sn[256], s_en[256], s_s0[256], s_e0[256];
    __shared__ int s_Nb;

    const int b = blockIdx.y;
    const int tid = threadIdx.y * blockDim.x + threadIdx.x;

    if (tid < n_max) {
        const int base = b * n_max + tid;
        s_sn[tid] = g_sn[base];
        s_en[tid] = g_en[base];
        s_s0[tid] = g_s0[base];
        s_e0[tid] = g_e0[base];
    }
    if (tid == 0) s_Nb = Narr[b];
    __syncthreads();

    const int t = blockIdx.x * blockDim.x + threadIdx.x;
    if (t >= w_out) return;

    const int Nb = s_Nb;
    int lo = 0, hi = n_max;
    while (lo < hi) {
        const int mid = (lo + hi) >> 1;
        const int e = (mid < Nb) ? s_en[mid] : INT_MAX;
        if (e <= t) lo = mid + 1; else hi = mid;
    }
    const int i = lo;
    const int ic = min(i, n_max - 1);
    const int sn_i = s_sn[ic], en_i = s_en[ic];
    const int s0_i = s_s0[ic], e0_i = s_e0[ic];
    const bool in_chirp = (i < Nb) && (t >= sn_i) && (en_i > sn_i) && (e0_i > s0_i);
    int src = min(max(s0_i + (t - sn_i), 0), W - 1);
    const int jp = min(max(i - 1, 0), n_max - 1);
    const int en_prev = s_en[jp];
    const bool is_sep = (i >= 1) && (t == en_prev) && ((i - 1) < (Nb - 1)) && (en_prev < W);
    const float fill = is_sep ? sep_param[0] : 0.0f;

    const float* __restrict__ xcol = x + (size_t)b * rows * W + src;
    float* __restrict__ ocol = out_x + (size_t)b * rows * w_out + t;
    const int ystep = blockDim.y;

    if (in_chirp) {
        int h = threadIdx.y;
        for (; h + 7 * ystep < rows; h += 8 * ystep) {
            float v[8];
            #pragma unroll
            for (int k = 0; k < 8; k++)
                v[k] = __ldcs(xcol + (size_t)(h + k * ystep) * W);
            #pragma unroll
            for (int k = 0; k < 8; k++)
                __stcs(ocol + (size_t)(h + k * ystep) * w_out, v[k]);
        }
        for (; h < rows; h += ystep)
            __stcs(ocol + (size_t)h * w_out, __ldcs(xcol + (size_t)h * W));
    } else {
        for (int h = threadIdx.y; h < rows; h += ystep)
            __stcs(ocol + (size_t)h * w_out, fill);
    }

    if (threadIdx.y == 0) {
        int xlv = in_chirp ? xl[b * W + src] : (is_sep ? 2 : 0);
        out_xl[(size_t)b * w_out + t] = (float)xlv;
    }
}

// ---------------------------------------------------------------------------
// Launch.
// ---------------------------------------------------------------------------
extern "C" void kernel_launch(void* const* d_in, const int* in_sizes, int n_in,
                              void* d_out, int out_size)
{
    const float* x   = (const float*)d_in[0];
    const int*   xi  = (const int*)  d_in[1];
    const int*   Nn  = (const int*)  d_in[2];
    const int*   xl  = (const int*)  d_in[3];
    const float* sep = (const float*)d_in[4];

    const int B     = in_sizes[2];
    const int n_max = in_sizes[1] / (2 * B);
    const int W     = in_sizes[3] / B;
    const int rows  = in_sizes[0] / (B * W);           // C * H
    const int w_out = (out_size - B * n_max * 2) / (B * (rows + 1));

    float* out_x  = (float*)d_out;
    float* out_xi = out_x + (size_t)B * rows * w_out;
    float* out_xl = out_xi + (size_t)B * n_max * 2;

    tb_meta_kernel<<<B, n_max, n_max * sizeof(int)>>>(xi, Nn, out_xi, n_max);

    dim3 block(128, 2);
    dim3 grid((w_out + 127) / 128, B);

    if (rows == 128 && W == 8192 && w_out == 6271 && n_max == 128) {
        tb_main_tpl<128, 8192, 6271, 128><<<grid, block>>>(
            x, xl, sep, Nn, out_x, out_xl);
    } else {
        tb_main_kernel<<<grid, block>>>(x, xl, sep, Nn, out_x, out_xl,
                                        rows, W, w_out, n_max);
    }
}